// round 5
// baseline (speedup 1.0000x reference)
#include <cuda_runtime.h>

#define BB 2
#define CC 64
#define HH 96
#define WW 192
#define DD 48
#define GG 8
#define HW (HH*WW)

// ---------------- scratch (static device globals; no allocation) ----------------
__device__ float g_fln[BB*GG*HW*8];          // [b][g][h][w][c]  (9.4 MB)
__device__ float g_frn[BB*GG*HW*8];          // [b][g][h][w][c]
__device__ float g_base[(size_t)BB*DD*GG*HW];// [b][d][g][h][w]  (56.6 MB)
__device__ float g_sw[BB*HW*3];              // [b][h][w][s]
__device__ float g_wpack[3*27*64];           // [s][tap][gi][g]
__device__ float g_w1pack[65*9*32];          // [ic][tap][oc]
__device__ float g_bnscale[32];
__device__ float g_bnbias[32];

// ---------------- f32x2 helpers ----------------
__device__ __forceinline__ unsigned long long pk2(float lo, float hi) {
    unsigned long long r;
    asm("mov.b64 %0, {%1, %2};" : "=l"(r) : "f"(lo), "f"(hi));
    return r;
}
__device__ __forceinline__ void upk2(float& lo, float& hi, unsigned long long v) {
    asm("mov.b64 {%0, %1}, %2;" : "=f"(lo), "=f"(hi) : "l"(v));
}
__device__ __forceinline__ void fma2(unsigned long long& d, unsigned long long a,
                                     unsigned long long b) {
    asm("fma.rn.f32x2 %0, %1, %2, %0;" : "+l"(d) : "l"(a), "l"(b));
}

// ---------------- K0: repack weights ----------------
__global__ void k_prep(const float* __restrict__ w_s, const float* __restrict__ w_m,
                       const float* __restrict__ w_l, const float* __restrict__ w_pred1,
                       const float* __restrict__ gamma, const float* __restrict__ beta,
                       const float* __restrict__ mean, const float* __restrict__ var) {
    int tid = blockIdx.x * blockDim.x + threadIdx.x;
    int stride = gridDim.x * blockDim.x;
    // 3d conv weights: src (g, gi, kd, kh, kw) -> dst [s][t][gi][g]
    for (int i = tid; i < 3*27*64; i += stride) {
        int g  = i & 7;
        int gi = (i >> 3) & 7;
        int t  = (i >> 6) % 27;
        int s  = i / (27*64);
        const float* w = (s == 0) ? w_s : ((s == 1) ? w_m : w_l);
        g_wpack[i] = w[(g*8 + gi)*27 + t];
    }
    // pred1 weights: src (oc, ic, kh, kw) -> dst [ic][t][oc]
    for (int i = tid; i < 65*9*32; i += stride) {
        int oc = i & 31;
        int t  = (i >> 5) % 9;
        int ic = i / 288;
        g_w1pack[i] = w_pred1[(oc*65 + ic)*9 + t];
    }
    if (tid < 32) {
        float sc = gamma[tid] * rsqrtf(var[tid] + 1e-5f);
        g_bnscale[tid] = sc;
        g_bnbias[tid]  = beta[tid] - mean[tid]*sc;
    }
}

// ---------------- K1: per-group L2 normalize, transpose to channel-last ----------------
__global__ void k_norm(const float* __restrict__ fl, const float* __restrict__ fr) {
    int idx = blockIdx.x * blockDim.x + threadIdx.x;   // over BB*GG*HW
    if (idx >= BB*GG*HW) return;
    int pix = idx % HW;
    int bg  = idx / HW;  // b*8+g
    const float* pl = fl + (size_t)bg*8*HW + pix;
    const float* pr = fr + (size_t)bg*8*HW + pix;
    float vl[8], vr[8];
    float sl = 0.f, sr = 0.f;
#pragma unroll
    for (int c = 0; c < 8; c++) {
        vl[c] = pl[c*HW]; sl += vl[c]*vl[c];
        vr[c] = pr[c*HW]; sr += vr[c]*vr[c];
    }
    float il = 1.0f / fmaxf(sqrtf(sl), 1e-12f);
    float ir = 1.0f / fmaxf(sqrtf(sr), 1e-12f);
    float* ol = g_fln + (size_t)idx*8;
    float* orr = g_frn + (size_t)idx*8;
#pragma unroll
    for (int c = 0; c < 8; c++) { ol[c] = vl[c]*il; orr[c] = vr[c]*ir; }
}

// ---------------- K2: correlation volume ----------------
__global__ void k_corr() {
    int idx = blockIdx.x * blockDim.x + threadIdx.x;   // over BB*GG*HW
    if (idx >= BB*GG*HW) return;
    int w = idx % WW;
    int rest = idx / WW;
    int h = rest % HH;
    int bg = rest / HH;
    int g = bg & 7, b = bg >> 3;
    const float4* fl4 = (const float4*)(g_fln + (size_t)idx*8);
    float4 a0 = fl4[0], a1 = fl4[1];
    const float inv = 0.35355339059327373f;  // 1/sqrt(8)
    const float* frrow = g_frn + ((size_t)(bg*HH + h)*WW)*8;
    float* op = g_base + ((size_t)b*DD*GG + g)*HW + h*WW + w;
    for (int d = 0; d < DD; d++) {
        float val = 0.f;
        if (w >= d) {
            const float4* f4 = (const float4*)(frrow + (size_t)(w - d)*8);
            float4 b0 = f4[0], b1 = f4[1];
            val = (a0.x*b0.x + a0.y*b0.y + a0.z*b0.z + a0.w*b0.w +
                   a1.x*b1.x + a1.y*b1.y + a1.z*b1.z + a1.w*b1.w) * inv;
        }
        op[(size_t)d*GG*HW] = val;
    }
}

// ---------------- K3: predictor branch -> softmax weights ----------------
__global__ void __launch_bounds__(192) k_pred(const float* __restrict__ feat_l,
                                              const float* __restrict__ edge,
                                              const float* __restrict__ w2,
                                              const float* __restrict__ b2,
                                              const float* __restrict__ temp) {
    __shared__ __align__(16) float sW[33*9*32];  // 38016 B chunk
    __shared__ float sScale[32], sBias[32], sW2[96], sB2[3];
    int tid = threadIdx.x;
    if (tid < 32) { sScale[tid] = g_bnscale[tid]; sBias[tid] = g_bnbias[tid]; }
    if (tid < 96) sW2[tid] = w2[tid];
    if (tid < 3)  sB2[tid] = b2[tid];

    int w = tid;               // 0..191
    int h = blockIdx.x % HH;
    int b = blockIdx.x / HH;

    float acc[32];
#pragma unroll
    for (int o = 0; o < 32; o++) acc[o] = 0.f;

    for (int c0 = 0; c0 < 65; c0 += 33) {
        int cn = min(33, 65 - c0);
        __syncthreads();
        for (int i = tid; i < cn*288; i += 192) sW[i] = g_w1pack[c0*288 + i];
        __syncthreads();
        for (int ic2 = 0; ic2 < cn; ic2++) {
            int ic = c0 + ic2;
            const float* xin = (ic < 64) ? (feat_l + (size_t)(b*64 + ic)*HW)
                                         : (edge + (size_t)b*HW);
#pragma unroll
            for (int kh = 0; kh < 3; kh++) {
                int hh = h + kh - 1;
                if ((unsigned)hh >= HH) continue;
#pragma unroll
                for (int kw = 0; kw < 3; kw++) {
                    int ww = w + kw - 1;
                    if ((unsigned)ww >= WW) continue;
                    float xv = xin[hh*WW + ww];
                    const float4* wp = (const float4*)&sW[(ic2*9 + kh*3 + kw)*32];
#pragma unroll
                    for (int j = 0; j < 8; j++) {
                        float4 wv = wp[j];
                        acc[4*j+0] += xv*wv.x;
                        acc[4*j+1] += xv*wv.y;
                        acc[4*j+2] += xv*wv.z;
                        acc[4*j+3] += xv*wv.w;
                    }
                }
            }
        }
    }
    // BN + ReLU + 1x1 conv -> logits
    float l0 = sB2[0], l1 = sB2[1], l2 = sB2[2];
#pragma unroll
    for (int o = 0; o < 32; o++) {
        float hv = fmaxf(acc[o]*sScale[o] + sBias[o], 0.f);
        l0 += sW2[o]      * hv;
        l1 += sW2[32 + o] * hv;
        l2 += sW2[64 + o] * hv;
    }
    float t = fmaxf(temp[0], 0.1f);
    l0 /= t; l1 /= t; l2 /= t;
    float m = fmaxf(l0, fmaxf(l1, l2));
    float e0 = expf(l0 - m), e1 = expf(l1 - m), e2 = expf(l2 - m);
    float r = 1.0f / (e0 + e1 + e2);
    float* op = g_sw + ((size_t)(b*HH + h)*WW + w)*3;
    op[0] = e0*r; op[1] = e1*r; op[2] = e2*r;
}

// ---------------- K4: fused 3-scale dilated conv3d + blend + 1x1x1 ----------------
__global__ void __launch_bounds__(192) k_fuse(const float* __restrict__ wf,
                                              const float* __restrict__ bfin,
                                              float* __restrict__ out) {
    __shared__ __align__(16) float sWt[3*27*64];   // 20736 B
    __shared__ float sWf[256], sBf[32];
    int tid = threadIdx.x;
    for (int i = tid; i < 3*27*64; i += 192) sWt[i] = g_wpack[i];
    for (int i = tid; i < 256; i += 192) sWf[i] = wf[i];
    if (tid < 32) sBf[tid] = bfin[tid];
    __syncthreads();

    int w  = tid;                  // 0..191
    int h  = blockIdx.x % HH;
    int bd = blockIdx.x / HH;      // b*24 + dq
    int dq = bd % 24;
    int b  = bd / 24;
    int d0 = dq*2;                 // two d outputs per thread: d0, d0+1

    unsigned long long acc[2][3][4];
#pragma unroll
    for (int p = 0; p < 2; p++)
#pragma unroll
        for (int s = 0; s < 3; s++)
#pragma unroll
            for (int j = 0; j < 4; j++) acc[p][s][j] = 0ull;

    const float* bb = g_base + (size_t)b*DD*GG*HW;

#pragma unroll
    for (int s = 0; s < 3; s++) {
        const int dil = 1 << s;
#pragma unroll 1
        for (int kd = 0; kd < 3; kd++) {
            int dd0 = d0 + (kd - 1)*dil;
            bool vd0 = (unsigned)dd0 < DD;
            bool vd1 = (unsigned)(dd0 + 1) < DD;
#pragma unroll 1
            for (int kh = 0; kh < 3; kh++) {
                int hh = h + (kh - 1)*dil;
                bool vh = (unsigned)hh < HH;
#pragma unroll
                for (int kw = 0; kw < 3; kw++) {
                    int ww = w + (kw - 1)*dil;
                    bool vw = (unsigned)ww < WW;
                    bool v0 = vd0 & vh & vw;
                    bool v1 = vd1 & vh & vw;
                    if (!(v0 | v1)) continue;
                    int t = (kd*3 + kh)*3 + kw;
                    const float* wrow = &sWt[(s*27 + t)*64];
                    const float* bp = bb + (size_t)dd0*GG*HW + hh*WW + ww;
#pragma unroll
                    for (int gi = 0; gi < 8; gi++) {
                        float bv0 = v0 ? bp[gi*HW] : 0.f;
                        float bv1 = v1 ? bp[GG*HW + gi*HW] : 0.f;
                        unsigned long long p0 = pk2(bv0, bv0);
                        unsigned long long p1 = pk2(bv1, bv1);
                        const ulonglong2* wp = (const ulonglong2*)(wrow + gi*8);
                        ulonglong2 wa = wp[0], wb = wp[1];
                        fma2(acc[0][s][0], wa.x, p0); fma2(acc[1][s][0], wa.x, p1);
                        fma2(acc[0][s][1], wa.y, p0); fma2(acc[1][s][1], wa.y, p1);
                        fma2(acc[0][s][2], wb.x, p0); fma2(acc[1][s][2], wb.x, p1);
                        fma2(acc[0][s][3], wb.y, p0); fma2(acc[1][s][3], wb.y, p1);
                    }
                }
            }
        }
    }

    // per-pixel softmax blend + 1x1x1 conv to 32 channels
    const float* swp = g_sw + ((size_t)(b*HH + h)*WW + w)*3;
    float sw0 = swp[0], sw1 = swp[1], sw2 = swp[2];

#pragma unroll
    for (int pd = 0; pd < 2; pd++) {
        float fused[8];
#pragma unroll
        for (int j = 0; j < 4; j++) {
            float a0, b0, a1, b1, a2, b2;
            upk2(a0, b0, acc[pd][0][j]);
            upk2(a1, b1, acc[pd][1][j]);
            upk2(a2, b2, acc[pd][2][j]);
            fused[2*j]     = sw0*a0 + sw1*a1 + sw2*a2;
            fused[2*j + 1] = sw0*b0 + sw1*b1 + sw2*b2;
        }
        int d = d0 + pd;
        float* op = out + (((size_t)b*32*DD + d)*HH + h)*WW + w;
#pragma unroll
        for (int o = 0; o < 32; o++) {
            float v = sBf[o];
            const float* wfo = &sWf[o*8];
#pragma unroll
            for (int g = 0; g < 8; g++) v += wfo[g]*fused[g];
            op[(size_t)o*DD*HW] = v;
        }
    }
}

// ---------------- launch ----------------
extern "C" void kernel_launch(void* const* d_in, const int* in_sizes, int n_in,
                              void* d_out, int out_size) {
    const float* feat_l  = (const float*)d_in[0];
    const float* feat_r  = (const float*)d_in[1];
    const float* edge    = (const float*)d_in[2];
    const float* w_pred1 = (const float*)d_in[3];
    const float* gamma   = (const float*)d_in[4];
    const float* beta    = (const float*)d_in[5];
    const float* mean    = (const float*)d_in[6];
    const float* var     = (const float*)d_in[7];
    const float* w_pred2 = (const float*)d_in[8];
    const float* b_pred2 = (const float*)d_in[9];
    const float* temp    = (const float*)d_in[10];
    const float* w_s     = (const float*)d_in[11];
    const float* w_m     = (const float*)d_in[12];
    const float* w_l     = (const float*)d_in[13];
    const float* w_final = (const float*)d_in[14];
    const float* b_final = (const float*)d_in[15];
    float* out = (float*)d_out;

    k_prep<<<32, 256>>>(w_s, w_m, w_l, w_pred1, gamma, beta, mean, var);
    k_norm<<<(BB*GG*HW + 255)/256, 256>>>(feat_l, feat_r);
    k_corr<<<(BB*GG*HW + 255)/256, 256>>>();
    k_pred<<<BB*HH, 192>>>(feat_l, edge, w_pred2, b_pred2, temp);
    k_fuse<<<BB*24*HH, 192>>>(w_final, b_final, out);
}

// round 6
// speedup vs baseline: 1.0032x; 1.0032x over previous
#include <cuda_runtime.h>

#define BB 2
#define CC 64
#define HH 96
#define WW 192
#define DD 48
#define GG 8
#define HW (HH*WW)

// ---------------- scratch (static device globals; no allocation) ----------------
__device__ float g_fln[BB*GG*HW*8];          // [b][g][h][w][c]  (9.4 MB)
__device__ float g_frn[BB*GG*HW*8];          // [b][g][h][w][c]
__device__ float g_base[(size_t)BB*DD*GG*HW];// [b][d][g][h][w]  (56.6 MB)
__device__ float g_sw[BB*HW*3];              // [b][h][w][s]
__device__ float g_wpack[3*27*64];           // [s][tap][gi][g]
__device__ float g_w1pack[65*9*32];          // [ic][tap][oc]
__device__ float g_bnscale[32];
__device__ float g_bnbias[32];

// ---------------- f32x2 helpers ----------------
__device__ __forceinline__ unsigned long long pk2(float lo, float hi) {
    unsigned long long r;
    asm("mov.b64 %0, {%1, %2};" : "=l"(r) : "f"(lo), "f"(hi));
    return r;
}
__device__ __forceinline__ void upk2(float& lo, float& hi, unsigned long long v) {
    asm("mov.b64 {%0, %1}, %2;" : "=f"(lo), "=f"(hi) : "l"(v));
}
__device__ __forceinline__ void fma2(unsigned long long& d, unsigned long long a,
                                     unsigned long long b) {
    asm("fma.rn.f32x2 %0, %1, %2, %0;" : "+l"(d) : "l"(a), "l"(b));
}

// ---------------- K0: repack weights ----------------
__global__ void k_prep(const float* __restrict__ w_s, const float* __restrict__ w_m,
                       const float* __restrict__ w_l, const float* __restrict__ w_pred1,
                       const float* __restrict__ gamma, const float* __restrict__ beta,
                       const float* __restrict__ mean, const float* __restrict__ var) {
    int tid = blockIdx.x * blockDim.x + threadIdx.x;
    int stride = gridDim.x * blockDim.x;
    // 3d conv weights: src (g, gi, kd, kh, kw) -> dst [s][t][gi][g]
    for (int i = tid; i < 3*27*64; i += stride) {
        int g  = i & 7;
        int gi = (i >> 3) & 7;
        int t  = (i >> 6) % 27;
        int s  = i / (27*64);
        const float* w = (s == 0) ? w_s : ((s == 1) ? w_m : w_l);
        g_wpack[i] = w[(g*8 + gi)*27 + t];
    }
    // pred1 weights: src (oc, ic, kh, kw) -> dst [ic][t][oc]
    for (int i = tid; i < 65*9*32; i += stride) {
        int oc = i & 31;
        int t  = (i >> 5) % 9;
        int ic = i / 288;
        g_w1pack[i] = w_pred1[(oc*65 + ic)*9 + t];
    }
    if (tid < 32) {
        float sc = gamma[tid] * rsqrtf(var[tid] + 1e-5f);
        g_bnscale[tid] = sc;
        g_bnbias[tid]  = beta[tid] - mean[tid]*sc;
    }
}

// ---------------- K1: per-group L2 normalize, transpose to channel-last ----------------
__global__ void k_norm(const float* __restrict__ fl, const float* __restrict__ fr) {
    int idx = blockIdx.x * blockDim.x + threadIdx.x;   // over BB*GG*HW
    if (idx >= BB*GG*HW) return;
    int pix = idx % HW;
    int bg  = idx / HW;  // b*8+g
    const float* pl = fl + (size_t)bg*8*HW + pix;
    const float* pr = fr + (size_t)bg*8*HW + pix;
    float vl[8], vr[8];
    float sl = 0.f, sr = 0.f;
#pragma unroll
    for (int c = 0; c < 8; c++) {
        vl[c] = pl[c*HW]; sl += vl[c]*vl[c];
        vr[c] = pr[c*HW]; sr += vr[c]*vr[c];
    }
    float il = 1.0f / fmaxf(sqrtf(sl), 1e-12f);
    float ir = 1.0f / fmaxf(sqrtf(sr), 1e-12f);
    float* ol = g_fln + (size_t)idx*8;
    float* orr = g_frn + (size_t)idx*8;
#pragma unroll
    for (int c = 0; c < 8; c++) { ol[c] = vl[c]*il; orr[c] = vr[c]*ir; }
}

// ---------------- K2: correlation volume ----------------
__global__ void k_corr() {
    int idx = blockIdx.x * blockDim.x + threadIdx.x;   // over BB*GG*HW
    if (idx >= BB*GG*HW) return;
    int w = idx % WW;
    int rest = idx / WW;
    int h = rest % HH;
    int bg = rest / HH;
    int g = bg & 7, b = bg >> 3;
    const float4* fl4 = (const float4*)(g_fln + (size_t)idx*8);
    float4 a0 = fl4[0], a1 = fl4[1];
    const float inv = 0.35355339059327373f;  // 1/sqrt(8)
    const float* frrow = g_frn + ((size_t)(bg*HH + h)*WW)*8;
    float* op = g_base + ((size_t)b*DD*GG + g)*HW + h*WW + w;
    for (int d = 0; d < DD; d++) {
        float val = 0.f;
        if (w >= d) {
            const float4* f4 = (const float4*)(frrow + (size_t)(w - d)*8);
            float4 b0 = f4[0], b1 = f4[1];
            val = (a0.x*b0.x + a0.y*b0.y + a0.z*b0.z + a0.w*b0.w +
                   a1.x*b1.x + a1.y*b1.y + a1.z*b1.z + a1.w*b1.w) * inv;
        }
        op[(size_t)d*GG*HW] = val;
    }
}

// ---------------- K3: predictor branch -> softmax weights ----------------
__global__ void __launch_bounds__(192) k_pred(const float* __restrict__ feat_l,
                                              const float* __restrict__ edge,
                                              const float* __restrict__ w2,
                                              const float* __restrict__ b2,
                                              const float* __restrict__ temp) {
    __shared__ __align__(16) float sW[33*9*32];  // 38016 B chunk
    __shared__ float sScale[32], sBias[32], sW2[96], sB2[3];
    int tid = threadIdx.x;
    if (tid < 32) { sScale[tid] = g_bnscale[tid]; sBias[tid] = g_bnbias[tid]; }
    if (tid < 96) sW2[tid] = w2[tid];
    if (tid < 3)  sB2[tid] = b2[tid];

    int w = tid;               // 0..191
    int h = blockIdx.x % HH;
    int b = blockIdx.x / HH;

    float acc[32];
#pragma unroll
    for (int o = 0; o < 32; o++) acc[o] = 0.f;

    for (int c0 = 0; c0 < 65; c0 += 33) {
        int cn = min(33, 65 - c0);
        __syncthreads();
        for (int i = tid; i < cn*288; i += 192) sW[i] = g_w1pack[c0*288 + i];
        __syncthreads();
        for (int ic2 = 0; ic2 < cn; ic2++) {
            int ic = c0 + ic2;
            const float* xin = (ic < 64) ? (feat_l + (size_t)(b*64 + ic)*HW)
                                         : (edge + (size_t)b*HW);
#pragma unroll
            for (int kh = 0; kh < 3; kh++) {
                int hh = h + kh - 1;
                if ((unsigned)hh >= HH) continue;
#pragma unroll
                for (int kw = 0; kw < 3; kw++) {
                    int ww = w + kw - 1;
                    if ((unsigned)ww >= WW) continue;
                    float xv = xin[hh*WW + ww];
                    const float4* wp = (const float4*)&sW[(ic2*9 + kh*3 + kw)*32];
#pragma unroll
                    for (int j = 0; j < 8; j++) {
                        float4 wv = wp[j];
                        acc[4*j+0] += xv*wv.x;
                        acc[4*j+1] += xv*wv.y;
                        acc[4*j+2] += xv*wv.z;
                        acc[4*j+3] += xv*wv.w;
                    }
                }
            }
        }
    }
    // BN + ReLU + 1x1 conv -> logits
    float l0 = sB2[0], l1 = sB2[1], l2 = sB2[2];
#pragma unroll
    for (int o = 0; o < 32; o++) {
        float hv = fmaxf(acc[o]*sScale[o] + sBias[o], 0.f);
        l0 += sW2[o]      * hv;
        l1 += sW2[32 + o] * hv;
        l2 += sW2[64 + o] * hv;
    }
    float t = fmaxf(temp[0], 0.1f);
    l0 /= t; l1 /= t; l2 /= t;
    float m = fmaxf(l0, fmaxf(l1, l2));
    float e0 = expf(l0 - m), e1 = expf(l1 - m), e2 = expf(l2 - m);
    float r = 1.0f / (e0 + e1 + e2);
    float* op = g_sw + ((size_t)(b*HH + h)*WW + w)*3;
    op[0] = e0*r; op[1] = e1*r; op[2] = e2*r;
}

// ---------------- K4: fused 3-scale dilated conv3d + blend + 1x1x1 ----------------
__global__ void __launch_bounds__(192) k_fuse(const float* __restrict__ wf,
                                              const float* __restrict__ bfin,
                                              float* __restrict__ out) {
    __shared__ __align__(16) float sWt[3*27*64];   // 20736 B
    __shared__ float sWf[256], sBf[32];
    int tid = threadIdx.x;
    for (int i = tid; i < 3*27*64; i += 192) sWt[i] = g_wpack[i];
    for (int i = tid; i < 256; i += 192) sWf[i] = wf[i];
    if (tid < 32) sBf[tid] = bfin[tid];
    __syncthreads();

    int w  = tid;                  // 0..191
    int h  = blockIdx.x % HH;
    int bd = blockIdx.x / HH;      // b*24 + dq
    int dq = bd % 24;
    int b  = bd / 24;
    int d0 = dq*2;                 // two d outputs per thread: d0, d0+1

    unsigned long long acc[2][3][4];
#pragma unroll
    for (int p = 0; p < 2; p++)
#pragma unroll
        for (int s = 0; s < 3; s++)
#pragma unroll
            for (int j = 0; j < 4; j++) acc[p][s][j] = 0ull;

    const float* bb = g_base + (size_t)b*DD*GG*HW;

#pragma unroll
    for (int s = 0; s < 3; s++) {
        const int dil = 1 << s;
#pragma unroll 1
        for (int kd = 0; kd < 3; kd++) {
            int dd0 = d0 + (kd - 1)*dil;
            bool vd0 = (unsigned)dd0 < DD;
            bool vd1 = (unsigned)(dd0 + 1) < DD;
#pragma unroll 1
            for (int kh = 0; kh < 3; kh++) {
                int hh = h + (kh - 1)*dil;
                bool vh = (unsigned)hh < HH;
#pragma unroll
                for (int kw = 0; kw < 3; kw++) {
                    int ww = w + (kw - 1)*dil;
                    bool vw = (unsigned)ww < WW;
                    bool v0 = vd0 & vh & vw;
                    bool v1 = vd1 & vh & vw;
                    if (!(v0 | v1)) continue;
                    int t = (kd*3 + kh)*3 + kw;
                    const float* wrow = &sWt[(s*27 + t)*64];
                    const float* bp = bb + (size_t)dd0*GG*HW + hh*WW + ww;
#pragma unroll
                    for (int gi = 0; gi < 8; gi++) {
                        float bv0 = v0 ? bp[gi*HW] : 0.f;
                        float bv1 = v1 ? bp[GG*HW + gi*HW] : 0.f;
                        unsigned long long p0 = pk2(bv0, bv0);
                        unsigned long long p1 = pk2(bv1, bv1);
                        const ulonglong2* wp = (const ulonglong2*)(wrow + gi*8);
                        ulonglong2 wa = wp[0], wb = wp[1];
                        fma2(acc[0][s][0], wa.x, p0); fma2(acc[1][s][0], wa.x, p1);
                        fma2(acc[0][s][1], wa.y, p0); fma2(acc[1][s][1], wa.y, p1);
                        fma2(acc[0][s][2], wb.x, p0); fma2(acc[1][s][2], wb.x, p1);
                        fma2(acc[0][s][3], wb.y, p0); fma2(acc[1][s][3], wb.y, p1);
                    }
                }
            }
        }
    }

    // per-pixel softmax blend + 1x1x1 conv to 32 channels
    const float* swp = g_sw + ((size_t)(b*HH + h)*WW + w)*3;
    float sw0 = swp[0], sw1 = swp[1], sw2 = swp[2];

#pragma unroll
    for (int pd = 0; pd < 2; pd++) {
        float fused[8];
#pragma unroll
        for (int j = 0; j < 4; j++) {
            float a0, b0, a1, b1, a2, b2;
            upk2(a0, b0, acc[pd][0][j]);
            upk2(a1, b1, acc[pd][1][j]);
            upk2(a2, b2, acc[pd][2][j]);
            fused[2*j]     = sw0*a0 + sw1*a1 + sw2*a2;
            fused[2*j + 1] = sw0*b0 + sw1*b1 + sw2*b2;
        }
        int d = d0 + pd;
        float* op = out + (((size_t)b*32*DD + d)*HH + h)*WW + w;
#pragma unroll
        for (int o = 0; o < 32; o++) {
            float v = sBf[o];
            const float* wfo = &sWf[o*8];
#pragma unroll
            for (int g = 0; g < 8; g++) v += wfo[g]*fused[g];
            op[(size_t)o*DD*HW] = v;
        }
    }
}

// ---------------- launch ----------------
extern "C" void kernel_launch(void* const* d_in, const int* in_sizes, int n_in,
                              void* d_out, int out_size) {
    const float* feat_l  = (const float*)d_in[0];
    const float* feat_r  = (const float*)d_in[1];
    const float* edge    = (const float*)d_in[2];
    const float* w_pred1 = (const float*)d_in[3];
    const float* gamma   = (const float*)d_in[4];
    const float* beta    = (const float*)d_in[5];
    const float* mean    = (const float*)d_in[6];
    const float* var     = (const float*)d_in[7];
    const float* w_pred2 = (const float*)d_in[8];
    const float* b_pred2 = (const float*)d_in[9];
    const float* temp    = (const float*)d_in[10];
    const float* w_s     = (const float*)d_in[11];
    const float* w_m     = (const float*)d_in[12];
    const float* w_l     = (const float*)d_in[13];
    const float* w_final = (const float*)d_in[14];
    const float* b_final = (const float*)d_in[15];
    float* out = (float*)d_out;

    k_prep<<<32, 256>>>(w_s, w_m, w_l, w_pred1, gamma, beta, mean, var);
    k_norm<<<(BB*GG*HW + 255)/256, 256>>>(feat_l, feat_r);
    k_corr<<<(BB*GG*HW + 255)/256, 256>>>();
    k_pred<<<BB*HH, 192>>>(feat_l, edge, w_pred2, b_pred2, temp);
    k_fuse<<<BB*24*HH, 192>>>(w_final, b_final, out);
}

// round 7
// speedup vs baseline: 1.2675x; 1.2634x over previous
#include <cuda_runtime.h>

#define BB 2
#define CC 64
#define HH 96
#define WW 192
#define DD 48
#define GG 8
#define HW (HH*WW)
#define NCH 4

// ---------------- scratch (static device globals; no allocation) ----------------
__device__ float g_fln[BB*GG*HW*8];              // [b][g][h][w][c]
__device__ float g_frn[BB*GG*HW*8];              // [b][g][h][w][c]
__device__ float g_base[(size_t)BB*DD*GG*HW];    // [b][d][g][h][w]
__device__ float g_sw2[3*BB*HW];                 // [s][b][hw]
__device__ float g_wpack2[10368];                // [s][kd][kh][gi][kw][g][dup]
__device__ float g_w1pack[65*9*32];              // [ic][tap][oc]
__device__ float g_pmid[NCH*BB*32*HW];           // partial conv32 outputs
__device__ float g_bnscale[32];
__device__ float g_bnbias[32];

// ---------------- f32x2 helpers ----------------
typedef unsigned long long ull;
__device__ __forceinline__ ull pk2(float lo, float hi) {
    ull r;
    asm("mov.b64 %0, {%1, %2};" : "=l"(r) : "f"(lo), "f"(hi));
    return r;
}
__device__ __forceinline__ void upk2(float& lo, float& hi, ull v) {
    asm("mov.b64 {%0, %1}, %2;" : "=f"(lo), "=f"(hi) : "l"(v));
}
__device__ __forceinline__ void fma2(ull& d, ull a, ull b) {
    asm("fma.rn.f32x2 %0, %1, %2, %0;" : "+l"(d) : "l"(a), "l"(b));
}

// ---------------- K0: repack weights ----------------
__global__ void k_prep(const float* __restrict__ w_s, const float* __restrict__ w_m,
                       const float* __restrict__ w_l, const float* __restrict__ w_pred1,
                       const float* __restrict__ gamma, const float* __restrict__ beta,
                       const float* __restrict__ mean, const float* __restrict__ var) {
    int tid = blockIdx.x * blockDim.x + threadIdx.x;
    int stride = gridDim.x * blockDim.x;
    // splatted 3d conv weights: dst [s][kd][kh][gi][kw][g][dup]
    for (int i = tid; i < 10368; i += stride) {
        int g  = (i >> 1) & 7;
        int kw = (i >> 4) % 3;
        int gi = (i / 48) & 7;
        int kh = (i / 384) % 3;
        int kd = (i / 1152) % 3;
        int s  = i / 3456;
        const float* w = (s == 0) ? w_s : ((s == 1) ? w_m : w_l);
        g_wpack2[i] = w[(g*8 + gi)*27 + (kd*3 + kh)*3 + kw];
    }
    // pred1 weights: src (oc, ic, kh, kw) -> dst [ic][t][oc]
    for (int i = tid; i < 65*9*32; i += stride) {
        int oc = i & 31;
        int t  = (i >> 5) % 9;
        int ic = i / 288;
        g_w1pack[i] = w_pred1[(oc*65 + ic)*9 + t];
    }
    if (tid < 32) {
        float sc = gamma[tid] * rsqrtf(var[tid] + 1e-5f);
        g_bnscale[tid] = sc;
        g_bnbias[tid]  = beta[tid] - mean[tid]*sc;
    }
}

// ---------------- K1: per-group L2 normalize, transpose to channel-last ----------------
__global__ void k_norm(const float* __restrict__ fl, const float* __restrict__ fr) {
    int idx = blockIdx.x * blockDim.x + threadIdx.x;   // over BB*GG*HW
    if (idx >= BB*GG*HW) return;
    int pix = idx % HW;
    int bg  = idx / HW;
    const float* pl = fl + (size_t)bg*8*HW + pix;
    const float* pr = fr + (size_t)bg*8*HW + pix;
    float vl[8], vr[8];
    float sl = 0.f, sr = 0.f;
#pragma unroll
    for (int c = 0; c < 8; c++) {
        vl[c] = pl[c*HW]; sl += vl[c]*vl[c];
        vr[c] = pr[c*HW]; sr += vr[c]*vr[c];
    }
    float il = 1.0f / fmaxf(sqrtf(sl), 1e-12f);
    float ir = 1.0f / fmaxf(sqrtf(sr), 1e-12f);
    float* ol = g_fln + (size_t)idx*8;
    float* orr = g_frn + (size_t)idx*8;
#pragma unroll
    for (int c = 0; c < 8; c++) { ol[c] = vl[c]*il; orr[c] = vr[c]*ir; }
}

// ---------------- K2: correlation volume ----------------
__global__ void k_corr() {
    int idx = blockIdx.x * blockDim.x + threadIdx.x;
    if (idx >= BB*GG*HW) return;
    int w = idx % WW;
    int rest = idx / WW;
    int h = rest % HH;
    int bg = rest / HH;
    int g = bg & 7, b = bg >> 3;
    const float4* fl4 = (const float4*)(g_fln + (size_t)idx*8);
    float4 a0 = fl4[0], a1 = fl4[1];
    const float inv = 0.35355339059327373f;
    const float* frrow = g_frn + ((size_t)(bg*HH + h)*WW)*8;
    float* op = g_base + ((size_t)b*DD*GG + g)*HW + h*WW + w;
    for (int d = 0; d < DD; d++) {
        float val = 0.f;
        if (w >= d) {
            const float4* f4 = (const float4*)(frrow + (size_t)(w - d)*8);
            float4 b0 = f4[0], b1 = f4[1];
            val = (a0.x*b0.x + a0.y*b0.y + a0.z*b0.z + a0.w*b0.w +
                   a1.x*b1.x + a1.y*b1.y + a1.z*b1.z + a1.w*b1.w) * inv;
        }
        op[(size_t)d*GG*HW] = val;
    }
}

// ---------------- K3a: predictor conv partials (ic-chunked) ----------------
__global__ void __launch_bounds__(192) k_pred_part(const float* __restrict__ feat_l,
                                                   const float* __restrict__ edge) {
    __shared__ __align__(16) float sW[17*9*32];
    int tid = threadIdx.x;
    int h = blockIdx.x % HH;
    int t2 = blockIdx.x / HH;
    int chunk = t2 % NCH;
    int b = t2 / NCH;
    int c0 = (chunk == 0) ? 0 : (17 + 16*(chunk - 1));
    int cn = (chunk == 0) ? 17 : 16;
    for (int i = tid; i < cn*288; i += 192) sW[i] = g_w1pack[c0*288 + i];
    __syncthreads();

    int w = tid;
    ull acc[16];
#pragma unroll
    for (int k = 0; k < 16; k++) acc[k] = 0ull;

    for (int ic2 = 0; ic2 < cn; ic2++) {
        int ic = c0 + ic2;
        const float* xin = (ic < 64) ? (feat_l + (size_t)(b*64 + ic)*HW)
                                     : (edge + (size_t)b*HW);
#pragma unroll
        for (int kh = 0; kh < 3; kh++) {
            int hh = h + kh - 1;
            if ((unsigned)hh >= HH) continue;
#pragma unroll
            for (int kw = 0; kw < 3; kw++) {
                int ww = w + kw - 1;
                if ((unsigned)ww >= WW) continue;
                float xv = xin[hh*WW + ww];
                ull xp = pk2(xv, xv);
                const ulonglong2* wp = (const ulonglong2*)&sW[(ic2*9 + kh*3 + kw)*32];
#pragma unroll
                for (int j = 0; j < 8; j++) {
                    ulonglong2 v = wp[j];
                    fma2(acc[2*j],   v.x, xp);
                    fma2(acc[2*j+1], v.y, xp);
                }
            }
        }
    }
    float* op = g_pmid + (size_t)chunk*(BB*32*HW) + (size_t)(b*32)*HW + h*WW + w;
#pragma unroll
    for (int k = 0; k < 16; k++) {
        float lo, hi; upk2(lo, hi, acc[k]);
        op[(size_t)(2*k)*HW]   = lo;
        op[(size_t)(2*k+1)*HW] = hi;
    }
}

// ---------------- K3b: combine partials + BN + ReLU + 1x1 + softmax ----------------
__global__ void k_pred_fin(const float* __restrict__ w2, const float* __restrict__ b2,
                           const float* __restrict__ temp) {
    int idx = blockIdx.x * blockDim.x + threadIdx.x;
    if (idx >= BB*HW) return;
    int b = idx / HW;
    int pix = idx % HW;
    float l0 = b2[0], l1 = b2[1], l2 = b2[2];
    const float* base = g_pmid + (size_t)(b*32)*HW + pix;
#pragma unroll 4
    for (int o = 0; o < 32; o++) {
        float v = 0.f;
#pragma unroll
        for (int c = 0; c < NCH; c++)
            v += base[(size_t)c*(BB*32*HW) + (size_t)o*HW];
        v = fmaxf(v*g_bnscale[o] + g_bnbias[o], 0.f);
        l0 += __ldg(&w2[o])      * v;
        l1 += __ldg(&w2[32 + o]) * v;
        l2 += __ldg(&w2[64 + o]) * v;
    }
    float t = fmaxf(temp[0], 0.1f);
    l0 /= t; l1 /= t; l2 /= t;
    float m = fmaxf(l0, fmaxf(l1, l2));
    float e0 = expf(l0 - m), e1 = expf(l1 - m), e2 = expf(l2 - m);
    float r = 1.0f / (e0 + e1 + e2);
    g_sw2[0*BB*HW + idx] = e0*r;
    g_sw2[1*BB*HW + idx] = e1*r;
    g_sw2[2*BB*HW + idx] = e2*r;
}

// ---------------- K4: fused 3-scale dilated conv3d + blend + 1x1x1 ----------------
// f32x2 lanes = pixel pair (w0, w0+1). One float2 LDG feeds both lanes.
__global__ void __launch_bounds__(192) k_fuse(const float* __restrict__ wf,
                                              const float* __restrict__ bfin,
                                              float* __restrict__ out) {
    __shared__ __align__(16) float sWt[10368];   // 41.5 KB splatted weights
    __shared__ __align__(16) float sWf2[512];
    __shared__ float sBf[32];
    int tid = threadIdx.x;
    for (int i = tid; i < 10368; i += 192) sWt[i] = g_wpack2[i];
    for (int i = tid; i < 512; i += 192) sWf2[i] = wf[i >> 1];
    if (tid < 32) sBf[tid] = bfin[tid];
    __syncthreads();

    int lw = tid % 96;
    int dz = tid / 96;          // 0..1 (warp-uniform)
    int w0 = lw * 2;
    int h  = blockIdx.x % HH;
    int bd = blockIdx.x / HH;
    int d  = (bd % 24)*2 + dz;
    int b  = bd / 24;

    ull acc[3][8];              // [s][g], lo=px0 hi=px1
#pragma unroll
    for (int s = 0; s < 3; s++)
#pragma unroll
        for (int g = 0; g < 8; g++) acc[s][g] = 0ull;

    const float* bb = g_base + (size_t)b*DD*GG*HW;

#pragma unroll
    for (int s = 0; s < 3; s++) {
        const int dil = 1 << s;
        const int aoff = (s == 2) ? 4 : 2;
        bool aok = (w0 >= aoff);
        bool cok = (w0 + aoff + 1 < WW);
#pragma unroll 1
        for (int kd = 0; kd < 3; kd++) {
            int dd = d + (kd - 1)*dil;
            if ((unsigned)dd >= DD) continue;
#pragma unroll 1
            for (int kh = 0; kh < 3; kh++) {
                int hh = h + (kh - 1)*dil;
                if ((unsigned)hh >= HH) continue;
                const float* row = bb + (size_t)dd*GG*HW + hh*WW;
                const float* swrow = &sWt[((s*3 + kd)*3 + kh)*384];
#pragma unroll
                for (int gi = 0; gi < 8; gi++) {
                    const float* p = row + gi*HW;
                    float2 A = make_float2(0.f, 0.f), C = make_float2(0.f, 0.f);
                    float2 Bv = *(const float2*)(p + w0);
                    if (aok) A = *(const float2*)(p + w0 - aoff);
                    if (cok) C = *(const float2*)(p + w0 + aoff);
                    ull p0, p1, p2;
                    p1 = pk2(Bv.x, Bv.y);
                    if (s == 0) { p0 = pk2(A.y, Bv.x); p2 = pk2(Bv.y, C.x); }
                    else        { p0 = pk2(A.x, A.y);  p2 = pk2(C.x, C.y);  }
                    const ulonglong2* wp = (const ulonglong2*)(swrow + gi*48);
#pragma unroll
                    for (int j = 0; j < 4; j++) {
                        ulonglong2 wv = wp[j];           // kw = 0
                        fma2(acc[s][2*j],   wv.x, p0);
                        fma2(acc[s][2*j+1], wv.y, p0);
                    }
#pragma unroll
                    for (int j = 0; j < 4; j++) {
                        ulonglong2 wv = wp[4 + j];       // kw = 1
                        fma2(acc[s][2*j],   wv.x, p1);
                        fma2(acc[s][2*j+1], wv.y, p1);
                    }
#pragma unroll
                    for (int j = 0; j < 4; j++) {
                        ulonglong2 wv = wp[8 + j];       // kw = 2
                        fma2(acc[s][2*j],   wv.x, p2);
                        fma2(acc[s][2*j+1], wv.y, p2);
                    }
                }
            }
        }
    }

    // epilogue: softmax blend (per-pixel f32x2) + 1x1x1 conv to 32 channels
    int pix0 = h*WW + w0;
    float2 s0 = *(const float2*)(g_sw2 + 0*BB*HW + b*HW + pix0);
    float2 s1 = *(const float2*)(g_sw2 + 1*BB*HW + b*HW + pix0);
    float2 s2 = *(const float2*)(g_sw2 + 2*BB*HW + b*HW + pix0);
    ull q0 = pk2(s0.x, s0.y), q1 = pk2(s1.x, s1.y), q2 = pk2(s2.x, s2.y);
    ull fu[8];
#pragma unroll
    for (int g = 0; g < 8; g++) {
        ull f = 0ull;
        fma2(f, q0, acc[0][g]);
        fma2(f, q1, acc[1][g]);
        fma2(f, q2, acc[2][g]);
        fu[g] = f;
    }
    float* op = out + (((size_t)b*32)*DD + d)*HW + pix0;
#pragma unroll
    for (int o = 0; o < 32; o++) {
        ull a = pk2(sBf[o], sBf[o]);
        const ulonglong2* wo = (const ulonglong2*)&sWf2[o*16];
#pragma unroll
        for (int j = 0; j < 4; j++) {
            ulonglong2 v = wo[j];
            fma2(a, v.x, fu[2*j]);
            fma2(a, v.y, fu[2*j+1]);
        }
        float lo, hi; upk2(lo, hi, a);
        __stcs((float2*)(op + (size_t)o*DD*HW), make_float2(lo, hi));
    }
}

// ---------------- launch ----------------
extern "C" void kernel_launch(void* const* d_in, const int* in_sizes, int n_in,
                              void* d_out, int out_size) {
    const float* feat_l  = (const float*)d_in[0];
    const float* feat_r  = (const float*)d_in[1];
    const float* edge    = (const float*)d_in[2];
    const float* w_pred1 = (const float*)d_in[3];
    const float* gamma   = (const float*)d_in[4];
    const float* beta    = (const float*)d_in[5];
    const float* mean    = (const float*)d_in[6];
    const float* var     = (const float*)d_in[7];
    const float* w_pred2 = (const float*)d_in[8];
    const float* b_pred2 = (const float*)d_in[9];
    const float* temp    = (const float*)d_in[10];
    const float* w_s     = (const float*)d_in[11];
    const float* w_m     = (const float*)d_in[12];
    const float* w_l     = (const float*)d_in[13];
    const float* w_final = (const float*)d_in[14];
    const float* b_final = (const float*)d_in[15];
    float* out = (float*)d_out;

    k_prep<<<32, 256>>>(w_s, w_m, w_l, w_pred1, gamma, beta, mean, var);
    k_norm<<<(BB*GG*HW + 255)/256, 256>>>(feat_l, feat_r);
    k_corr<<<(BB*GG*HW + 255)/256, 256>>>();
    k_pred_part<<<BB*HH*NCH, 192>>>(feat_l, edge);
    k_pred_fin<<<(BB*HW + 255)/256, 256>>>(w_pred2, b_pred2, temp);
    k_fuse<<<BB*24*HH, 192>>>(w_final, b_final, out);
}